// round 1
// baseline (speedup 1.0000x reference)
#include <cuda_runtime.h>
#include <math.h>

#define EPS_F 1e-8f

// Scratch accumulators (no device allocation allowed) — zeroed each launch.
__device__ double g_acc[6];

struct Q4 { float w, x, y, z; };

__device__ __forceinline__ Q4 qmult(const Q4 a, const Q4 b) {
    Q4 r;
    r.w = a.w * b.w - a.x * b.x - a.y * b.y - a.z * b.z;
    r.x = a.w * b.x + a.x * b.w + a.y * b.z - a.z * b.y;
    r.y = a.w * b.y - a.x * b.z + a.y * b.w + a.z * b.x;
    r.z = a.w * b.z + a.x * b.y - a.y * b.x + a.z * b.w;
    return r;
}

__device__ __forceinline__ Q4 qexp3(float vx, float vy, float vz) {
    float n = fmaxf(sqrtf(vx * vx + vy * vy + vz * vz), EPS_F);
    float s = sinf(n) / n;
    Q4 r;
    r.w = cosf(n);
    r.x = vx * s; r.y = vy * s; r.z = vz * s;
    return r;
}

__device__ __forceinline__ void qlog3(const Q4 q, float& ox, float& oy, float& oz) {
    float n = fmaxf(sqrtf(q.x * q.x + q.y * q.y + q.z * q.z), EPS_F);
    float f = acosf(fminf(fmaxf(q.w, -1.0f), 1.0f)) / n;
    ox = q.x * f; oy = q.y * f; oz = q.z * f;
}

__global__ void zero_acc_kernel() {
    if (threadIdx.x < 6) g_acc[threadIdx.x] = 0.0;
}

__global__ void __launch_bounds__(256) loss_kernel(
    const float* __restrict__ pred,
    const float* __restrict__ targ,
    const float* __restrict__ imu,
    int total /* N*T */)
{
    constexpr int T = 1024;
    float s0 = 0.f, s1 = 0.f, s2 = 0.f, s3 = 0.f, s4 = 0.f, s5 = 0.f;

    const int stride = gridDim.x * blockDim.x;
    for (int i = blockIdx.x * blockDim.x + threadIdx.x; i < total; i += stride) {
        const int t = i & (T - 1);

        // Current rows (8B-aligned: 6 floats * 4B = 24B offsets)
        const float2* pr = reinterpret_cast<const float2*>(pred + (size_t)i * 6);
        const float2* tg = reinterpret_cast<const float2*>(targ + (size_t)i * 6);
        float2 pA = pr[0], pB = pr[1], pC = pr[2];
        float2 gA = tg[0], gB = tg[1], gC = tg[2];
        float p0 = pA.x, p1 = pA.y, p2 = pB.x, p3 = pB.y, p4 = pC.x, p5 = pC.y;
        float g0 = gA.x, g1 = gA.y, g2 = gB.x, g3 = gB.y, g4 = gC.x, g5 = gC.y;

        // abs loss terms (all t)
        s0 += fabsf(p0 - g0) + fabsf(p1 - g1) + fabsf(p2 - g2);
        s1 += fabsf(p3 - g3) + fabsf(p4 - g4) + fabsf(p5 - g5);

        if (t < T - 1) {
            // Next rows (served from L1/L2 — owned by neighbor thread)
            const float2* pr1 = reinterpret_cast<const float2*>(pred + (size_t)(i + 1) * 6);
            const float2* tg1 = reinterpret_cast<const float2*>(targ + (size_t)(i + 1) * 6);
            float2 qA = pr1[0], qB = pr1[1], qC = pr1[2];
            float2 hA = tg1[0], hB = tg1[1], hC = tg1[2];
            float pp0 = qA.x, pp1 = qA.y, pp2 = qB.x, pp3 = qB.y, pp4 = qC.x, pp5 = qC.y;
            float h0 = hA.x, h1 = hA.y, h2 = hB.x, h3 = hB.y, h4 = hC.x, h5 = hC.y;

            // IMU row i: 10 floats, 8B-aligned
            const float2* im = reinterpret_cast<const float2*>(imu + (size_t)i * 10);
            float2 i01 = im[0], i23 = im[1], i45 = im[2], i67 = im[3], i89 = im[4];
            float ax = i01.x, ay = i01.y, az = i23.x;
            float vx = i23.y, vy = i45.x, vz = i45.y;
            float wx = i67.x, wy = i67.y, wz = i89.x;
            float ts0 = i89.y;
            float ts1 = imu[(size_t)(i + 1) * 10 + 9];

            // Quaternion exp of target orientations
            Q4 q0 = qexp3(g3, g4, g5);
            Q4 q1 = qexp3(h3, h4, h5);
            Q4 q0i; q0i.w = q0.w; q0i.x = -q0.x; q0i.y = -q0.y; q0i.z = -q0.z;

            // targ_imu_q = qlog(q0^-1 * q1)
            Q4 rel = qmult(q0i, q1);
            float tiqx, tiqy, tiqz;
            qlog3(rel, tiqx, tiqy, tiqz);

            // dt and IMU translation
            float dt = (ts1 - ts0) / 1e9f;
            float itx = vx * dt + 0.5f * ax * dt * dt;
            float ity = vy * dt + 0.5f * ay * dt * dt;
            float itz = vz * dt + 0.5f * az * dt * dt;

            // dq from angular velocity
            float wn = fmaxf(sqrtf(wx * wx + wy * wy + wz * wz), EPS_F);
            float half = 0.5f * (wn * dt);
            float sfac = sinf(half) / wn;
            Q4 dq; dq.w = cosf(half);
            dq.x = wx * sfac; dq.y = wy * sfac; dq.z = wz * sfac;

            // imu_ori_shift = qlog(q0^-1 * (q0 * dq))
            Q4 nq = qmult(q0, dq);
            Q4 shq = qmult(q0i, nq);
            float iox, ioy, ioz;
            qlog3(shq, iox, ioy, ioz);

            // velocities-of-state diffs
            float pvx = pp0 - p0, pvy = pp1 - p1, pvz = pp2 - p2;
            float pqx = pp3 - p3, pqy = pp4 - p4, pqz = pp5 - p5;
            float tvx = h0 - g0, tvy = h1 - g1, tvz = h2 - g2;
            float tqx = h3 - g3, tqy = h4 - g4, tqz = h5 - g5;

            s2 += fabsf(pvx - tvx) + fabsf(pvy - tvy) + fabsf(pvz - tvz);
            s3 += fabsf(pqx - tqx) + fabsf(pqy - tqy) + fabsf(pqz - tqz);
            s4 += fabsf(pvx - itx) + fabsf(pvy - ity) + fabsf(pvz - itz);
            s5 += fabsf(tiqx - iox) + fabsf(tiqy - ioy) + fabsf(tiqz - ioz);
        }
    }

    // ---- block reduction ----
    const unsigned FULL = 0xffffffffu;
    #pragma unroll
    for (int o = 16; o > 0; o >>= 1) {
        s0 += __shfl_xor_sync(FULL, s0, o);
        s1 += __shfl_xor_sync(FULL, s1, o);
        s2 += __shfl_xor_sync(FULL, s2, o);
        s3 += __shfl_xor_sync(FULL, s3, o);
        s4 += __shfl_xor_sync(FULL, s4, o);
        s5 += __shfl_xor_sync(FULL, s5, o);
    }

    __shared__ float sh[8 * 6];
    int wid = threadIdx.x >> 5;
    int lane = threadIdx.x & 31;
    if (lane == 0) {
        sh[wid * 6 + 0] = s0; sh[wid * 6 + 1] = s1; sh[wid * 6 + 2] = s2;
        sh[wid * 6 + 3] = s3; sh[wid * 6 + 4] = s4; sh[wid * 6 + 5] = s5;
    }
    __syncthreads();
    if (threadIdx.x == 0) {
        double a0 = 0, a1 = 0, a2 = 0, a3 = 0, a4 = 0, a5 = 0;
        int nw = blockDim.x >> 5;
        for (int w = 0; w < nw; w++) {
            a0 += sh[w * 6 + 0]; a1 += sh[w * 6 + 1]; a2 += sh[w * 6 + 2];
            a3 += sh[w * 6 + 3]; a4 += sh[w * 6 + 4]; a5 += sh[w * 6 + 5];
        }
        atomicAdd(&g_acc[0], a0); atomicAdd(&g_acc[1], a1);
        atomicAdd(&g_acc[2], a2); atomicAdd(&g_acc[3], a3);
        atomicAdd(&g_acc[4], a4); atomicAdd(&g_acc[5], a5);
    }
}

__global__ void finalize_kernel(
    const float* __restrict__ sax, const float* __restrict__ saq,
    const float* __restrict__ srx, const float* __restrict__ srq,
    float* __restrict__ out, double inv_abs, double inv_vo)
{
    float m1 = (float)(g_acc[0] * inv_abs);
    float m2 = (float)(g_acc[1] * inv_abs);
    float m3 = (float)(g_acc[2] * inv_vo);
    float m4 = (float)(g_acc[3] * inv_vo);
    float m5 = (float)(g_acc[4] * inv_vo);
    float m6 = (float)(g_acc[5] * inv_vo);

    float A = sax[0], B = saq[0], X = srx[0], Y = srq[0];

    float abs_loss = expf(-A) * m1 + A + expf(-B) * m2 + B;
    float vo_loss  = expf(-X) * m3 + X + expf(-Y) * m4 + Y;
    float imu_loss = expf(-X) * m5 + X + expf(-Y) * m6 + Y;

    out[0] = abs_loss + vo_loss + imu_loss;
}

extern "C" void kernel_launch(void* const* d_in, const int* in_sizes, int n_in,
                              void* d_out, int out_size)
{
    const float* pred = (const float*)d_in[0];
    const float* targ = (const float*)d_in[1];
    const float* imu  = (const float*)d_in[2];
    const float* sax  = (const float*)d_in[3];
    const float* saq  = (const float*)d_in[4];
    const float* srx  = (const float*)d_in[5];
    const float* srq  = (const float*)d_in[6];

    const int T = 1024;
    const int total = in_sizes[0] / 6;         // N*T
    const long long N = total / T;

    zero_acc_kernel<<<1, 32>>>();

    const int threads = 256;
    int blocks = 148 * 16; // 16 waves, keeps atomic count small
    int maxb = (total + threads - 1) / threads;
    if (blocks > maxb) blocks = maxb;
    loss_kernel<<<blocks, threads>>>(pred, targ, imu, total);

    double inv_abs = 1.0 / ((double)total * 3.0);
    double inv_vo  = 1.0 / ((double)N * (double)(T - 1) * 3.0);
    finalize_kernel<<<1, 1>>>(sax, saq, srx, srq, (float*)d_out, inv_abs, inv_vo);
}